// round 17
// baseline (speedup 1.0000x reference)
#include <cuda_runtime.h>
#include <cuda_fp16.h>
#include <cstdint>

#define B 256
#define L 128
#define F 256
#define S 512
#define BF (B*F)
#define G4F 1024

// ---- static device scratch (no allocation) ----
__device__ __half g_Wch[G4F * F];   // combined W_ih+W_hh, permuted [nf*128+c][k], fp16
__device__ float  g_WihT[G4F * F];  // [(nf*256+k)*128 + c]  (permuted c)
__device__ float  g_WhhT[G4F * F];
__device__ float  g_WiT[L * F];     // [k*256 + f]
__device__ float  g_bc[G4F];        // permuted combined bias
__device__ float  g_init[B * F];
__device__ float  g_c1[B * F];

__device__ __forceinline__ float sigf(float x) { return 1.0f / (1.0f + expf(-x)); }
__device__ __forceinline__ float tanhfast(float x) {
    float r; asm("tanh.approx.f32 %0, %1;" : "=f"(r) : "f"(x)); return r;
}
__device__ __forceinline__ float sigfast(float x) { return 0.5f * tanhfast(0.5f * x) + 0.5f; }

// ---- cluster / mbarrier helpers ----
__device__ __forceinline__ void mbar_init(uint32_t mbar, uint32_t cnt) {
    asm volatile("mbarrier.init.shared.b64 [%0], %1;" :: "r"(mbar), "r"(cnt) : "memory");
}
__device__ __forceinline__ void mbar_arrive_expect_tx(uint32_t mbar, uint32_t bytes) {
    asm volatile("mbarrier.arrive.expect_tx.shared.b64 _, [%0], %1;"
                 :: "r"(mbar), "r"(bytes) : "memory");
}
__device__ __forceinline__ void mbar_wait_cl(uint32_t mbar, uint32_t parity) {
    asm volatile(
        "{\n\t.reg .pred P;\n"
        "WL%=:\n\t"
        "mbarrier.try_wait.parity.acquire.cluster.shared::cta.b64 P, [%0], %1, 0x989680;\n\t"
        "@P bra WD%=;\n\t"
        "bra WL%=;\n"
        "WD%=:\n\t}"
        :: "r"(mbar), "r"(parity) : "memory");
}
__device__ __forceinline__ uint32_t mapa_u32(uint32_t local, uint32_t rank) {
    uint32_t r;
    asm("mapa.shared::cluster.u32 %0, %1, %2;" : "=r"(r) : "r"(local), "r"(rank));
    return r;
}
__device__ __forceinline__ void st_async_b32(uint32_t daddr, uint32_t v, uint32_t mbar) {
    asm volatile("st.async.shared::cluster.mbarrier::complete_tx::bytes.b32 [%0], %1, [%2];"
                 :: "r"(daddr), "r"(v), "r"(mbar) : "memory");
}
__device__ __forceinline__ uint32_t pack_h2(float a, float b) {
    __half2 h = __floats2half2_rn(a, b);
    return *(uint32_t*)&h;
}

// col permutation within a 128-col slice: c(j,g) = 16*(j>>2) + 2*(j&3) + (g&1) + 8*(g>>1)
// -> warp w owns cols [w*16, w*16+16): features j = w*4+tig, gates at thread cols
//    {2tig, 2tig+1} (gates i,f) and {8+2tig, 8+2tig+1} (gates g,o).
__global__ void prep_kernel(const float* __restrict__ Wih, const float* __restrict__ Whh,
                            const float* __restrict__ bih, const float* __restrict__ bhh,
                            const float* __restrict__ Wi) {
    int bid = blockIdx.x, tid = threadIdx.x;
    if (bid < 1024) {
        int r = bid, k = tid;
        int g = r >> 8;
        int jj = r & 255;
        int nf = jj >> 5;
        int j  = jj & 31;
        int c  = ((j >> 2) << 4) + ((j & 3) << 1) + (g & 1) + ((g >> 1) << 3);
        float wih = Wih[r * 256 + k];
        float whh = Whh[r * 256 + k];
        g_Wch[(nf * 128 + c) * 256 + k] = __float2half_rn(wih + whh);
        g_WihT[(nf * 256 + k) * 128 + c] = wih;
        g_WhhT[(nf * 256 + k) * 128 + c] = whh;
        if (k == 0) g_bc[nf * 128 + c] = bih[r] + bhh[r];
    } else {
        int k = bid - 1024;
        int f = tid;
        g_WiT[k * 256 + f] = Wi[f * 128 + k];
    }
}

// ---- P1: init = elu(x @ Wi.T + bi) ----
__global__ void init_kernel(const float* __restrict__ x, const float* __restrict__ bi) {
    __shared__ float xs[32 * 128];
    int bid = blockIdx.x, tid = threadIdx.x;
    int bt = bid >> 2, ft = bid & 3;
    for (int i = tid; i < 32 * 128; i += 256)
        xs[i] = x[(bt * 32 + (i >> 7)) * 128 + (i & 127)];
    __syncthreads();
    int tx = tid & 15, ty = tid >> 4;
    int b0 = ty * 2;
    int f0 = ft * 64 + tx * 4;
    float acc[2][4] = {};
#pragma unroll 4
    for (int k = 0; k < 128; ++k) {
        float4 w = *(const float4*)&g_WiT[k * 256 + f0];
        float x0 = xs[b0 * 128 + k];
        float x1 = xs[(b0 + 1) * 128 + k];
        acc[0][0] += x0 * w.x; acc[0][1] += x0 * w.y; acc[0][2] += x0 * w.z; acc[0][3] += x0 * w.w;
        acc[1][0] += x1 * w.x; acc[1][1] += x1 * w.y; acc[1][2] += x1 * w.z; acc[1][3] += x1 * w.w;
    }
#pragma unroll
    for (int r = 0; r < 2; ++r)
#pragma unroll
        for (int cc = 0; cc < 4; ++cc) {
            float v = acc[r][cc] + bi[f0 + cc];
            v = (v > 0.0f) ? v : expm1f(v);
            g_init[(bt * 32 + b0 + r) * 256 + f0 + cc] = v;
        }
}

// ---- P2: step 0 (inp = last_feat, h = c = init) ----
__global__ void step0_kernel(const float* __restrict__ lf, float* __restrict__ d_out) {
    extern __shared__ float sm[];
    float* lfs = sm;
    float* ins = lfs + 16 * 256;
    float* wih = ins + 16 * 256;
    float* whh = wih + 64 * 128;
    int tid = threadIdx.x;
    int nf = blockIdx.x & 7, mbt = blockIdx.x >> 3;
    for (int i = tid; i < 16 * 256; i += 256) {
        int gi = (mbt * 16 + (i >> 8)) * 256 + (i & 255);
        lfs[i] = lf[gi];
        ins[i] = g_init[gi];
    }
    int tx = tid & 31, ty = tid >> 5;
    int c0 = tx * 4;
    float acc[2][4] = {};
    for (int kc = 0; kc < 4; ++kc) {
        __syncthreads();
        for (int i = tid; i < 64 * 128; i += 256) {
            int k = kc * 64 + (i >> 7), c = i & 127;
            wih[i] = g_WihT[(nf * 256 + k) * 128 + c];
            whh[i] = g_WhhT[(nf * 256 + k) * 128 + c];
        }
        __syncthreads();
#pragma unroll 4
        for (int k = 0; k < 64; ++k) {
            float4 a4 = *(const float4*)&wih[k * 128 + c0];
            float4 b4 = *(const float4*)&whh[k * 128 + c0];
#pragma unroll
            for (int e = 0; e < 2; ++e) {
                int b = ty + 8 * e;
                float lv = lfs[b * 256 + kc * 64 + k];
                float iv = ins[b * 256 + kc * 64 + k];
                acc[e][0] += lv * a4.x + iv * b4.x;
                acc[e][1] += lv * a4.y + iv * b4.y;
                acc[e][2] += lv * a4.z + iv * b4.z;
                acc[e][3] += lv * a4.w + iv * b4.w;
            }
        }
    }
    __syncthreads();
    float* gss = lfs;
#pragma unroll
    for (int e = 0; e < 2; ++e)
#pragma unroll
        for (int cc = 0; cc < 4; ++cc)
            gss[(ty + 8 * e) * 132 + c0 + cc] = acc[e][cc];
    __syncthreads();
#pragma unroll
    for (int e2 = 0; e2 < 2; ++e2) {
        int li = tid + 256 * e2;
        int b = li >> 5, j = li & 31;
        int ci = ((j >> 2) << 4) + ((j & 3) << 1);   // gate i col; f=+1, g=+8, o=+9
        float iv = gss[b * 132 + ci]     + g_bc[nf * 128 + ci];
        float fv = gss[b * 132 + ci + 1] + g_bc[nf * 128 + ci + 1];
        float gv = gss[b * 132 + ci + 8] + g_bc[nf * 128 + ci + 8];
        float ov = gss[b * 132 + ci + 9] + g_bc[nf * 128 + ci + 9];
        float cp = ins[b * 256 + nf * 32 + j];
        float cn = sigf(fv) * cp + sigf(iv) * tanhf(gv);
        float hn = sigf(ov) * tanhf(cn);
        int gi = (mbt * 16 + b) * 256 + nf * 32 + j;
        g_c1[gi] = cn;
        d_out[gi] = hn;
    }
}

// ---- fp16 mma helper (m16n8k16, fp32 accum) ----
__device__ __forceinline__ void mma16(float* d, const unsigned* a, unsigned b0, unsigned b1) {
    asm volatile(
        "mma.sync.aligned.m16n8k16.row.col.f32.f16.f16.f32 "
        "{%0,%1,%2,%3}, {%4,%5,%6,%7}, {%8,%9}, {%0,%1,%2,%3};"
        : "+f"(d[0]), "+f"(d[1]), "+f"(d[2]), "+f"(d[3])
        : "r"(a[0]), "r"(a[1]), "r"(a[2]), "r"(a[3]), "r"(b0), "r"(b1));
}
__device__ __forceinline__ void ldsm_x4(unsigned* a, uint32_t addr) {
    asm volatile("ldmatrix.sync.aligned.m8n8.x4.shared.b16 {%0,%1,%2,%3}, [%4];"
                 : "=r"(a[0]), "=r"(a[1]), "=r"(a[2]), "=r"(a[3]) : "r"(addr));
}

#define HSTRIDE 264                 // halves per row (528 B)
#define HBUFB   (16 * HSTRIDE * 2)  // bytes per h buffer (8448)

// ---- P3: persistent recurrence, t = 1..511 ----
// 128 CTAs x 256 thr, clusters of 8 (= batch group mb). nf = bid&7.
// Full-k warps: warp w computes cols [w*16, w*16+16) over k=256 -> complete gates
// in registers, NO reduction, NO intra-step __syncthreads. One mbarrier per buffer,
// self-re-armed by per-warp arrive.expect_tx; data pushed via st.async (tx-credited).
__global__ void __cluster_dims__(8, 1, 1) __launch_bounds__(256, 1)
lstm_kernel(float* __restrict__ d_out) {
    __shared__ __align__(16) __half hs[2][16 * HSTRIDE];
    __shared__ __align__(8) unsigned long long mbars[2];   // one per buffer

    int tid = threadIdx.x;
    int nf = blockIdx.x & 7, mb = blockIdx.x >> 3;
    int warp = tid >> 5, lane = tid & 31;
    int gID = lane >> 2, tig = lane & 3;

    uint32_t hsb = (uint32_t)__cvta_generic_to_shared(&hs[0][0]);
    uint32_t mbb = (uint32_t)__cvta_generic_to_shared(&mbars[0]);

    if (tid == 0) { mbar_init(mbb, 8); mbar_init(mbb + 8, 8); }
    __syncthreads();
    if (lane == 0) {   // arm phase 0 of both buffers: 8 arrives x 1024 tx bytes
        mbar_arrive_expect_tx(mbb, 1024);
        mbar_arrive_expect_tx(mbb + 8, 1024);
    }

    // weight fragments: warp covers cols [warp*16,+16), full k=256
    unsigned breg[2][16][2];
#pragma unroll
    for (int nt = 0; nt < 2; ++nt)
#pragma unroll
        for (int kb = 0; kb < 16; ++kb) {
            const __half* wp = &g_Wch[(nf * 128 + warp * 16 + nt * 8 + gID) * 256
                                      + kb * 16 + 2 * tig];
            breg[nt][kb][0] = *(const uint32_t*)wp;
            breg[nt][kb][1] = *(const uint32_t*)(wp + 8);
        }

    float bias[2][2];
#pragma unroll
    for (int nt = 0; nt < 2; ++nt) {
        bias[nt][0] = g_bc[nf * 128 + warp * 16 + nt * 8 + 2 * tig];
        bias[nt][1] = g_bc[nf * 128 + warp * 16 + nt * 8 + 2 * tig + 1];
    }

    uint32_t peer_hs[8], peer_mb[8];
#pragma unroll
    for (int p = 0; p < 8; ++p) {
        peer_hs[p] = mapa_u32(hsb, p);
        peer_mb[p] = mapa_u32(mbb, p);
    }

    // cell state: feature j = warp*4+tig, rows gID and gID+8
    int j = warp * 4 + tig;
    float creg0 = g_c1[(mb * 16 + gID) * 256 + nf * 32 + j];
    float creg1 = g_c1[(mb * 16 + gID + 8) * 256 + nf * 32 + j];

    // push geometry: even tig -> row gID, odd tig -> row gID+8; feat base jp
    int jp = warp * 4 + (tig & 2);
    int myrow = (tig & 1) ? (gID + 8) : gID;
    uint32_t hoff = (uint32_t)(myrow * HSTRIDE + nf * 32 + jp) * 2;
    int dcol = nf * 32 + jp;

    // ldmatrix lane address: row (lane&7)+8*((lane>>3)&1), k-half (lane>>4)
    uint32_t lm_off = (uint32_t)(((lane & 7) + (((lane >> 3) & 1) << 3)) * (HSTRIDE * 2)
                                 + ((lane >> 4) << 4));

    __syncthreads();
    asm volatile("barrier.cluster.arrive.aligned;" ::: "memory");
    asm volatile("barrier.cluster.wait.aligned;" ::: "memory");

    // prologue: push own h_1 h2 (from d_out row 0) into buffer 1 everywhere
    {
        const float* src = d_out + (size_t)mb * 4096;
        float2 v = *(const float2*)(src + myrow * 256 + dcol);
        uint32_t hv = pack_h2(v.x, v.y);
#pragma unroll
        for (int p = 0; p < 8; ++p)
            st_async_b32(peer_hs[p] + HBUFB + hoff, hv, peer_mb[p] + 8);
    }

    unsigned ph[2] = {0u, 0u};

    for (int t = 1; t < 512; ++t) {
        int b = t & 1;
        uint32_t mybar = mbb + 8 * b;
        mbar_wait_cl(mybar, ph[b]);
        ph[b] ^= 1u;

        float acc[2][4];
#pragma unroll
        for (int nt = 0; nt < 2; ++nt) {
            acc[nt][0] = bias[nt][0]; acc[nt][1] = bias[nt][1];
            acc[nt][2] = bias[nt][0]; acc[nt][3] = bias[nt][1];
        }

        uint32_t lmb = hsb + (uint32_t)b * HBUFB + lm_off;
#pragma unroll
        for (int kb = 0; kb < 16; ++kb) {
            unsigned a[4];
            ldsm_x4(a, lmb + kb * 32);
            mma16(acc[0], a, breg[0][kb][0], breg[0][kb][1]);
            mma16(acc[1], a, breg[1][kb][0], breg[1][kb][1]);
        }

        // re-arm this buffer for t+2 (all reads of hs[b] by this warp are done)
        if (lane == 0 && t <= 509) mbar_arrive_expect_tx(mybar, 1024);

        // elementwise: gates i,f = acc[0][q&1], g,o = acc[1][q&1]; rows via q>>1
        float cn0 = sigfast(acc[0][1]) * creg0 + sigfast(acc[0][0]) * tanhfast(acc[1][0]);
        float h0  = sigfast(acc[1][1]) * tanhfast(cn0);
        creg0 = cn0;
        float cn1 = sigfast(acc[0][3]) * creg1 + sigfast(acc[0][2]) * tanhfast(acc[1][2]);
        float h1  = sigfast(acc[1][3]) * tanhfast(cn1);
        creg1 = cn1;

        // pair features via partner lane (lane^1 = same gID, tig^1)
        float p0 = __shfl_xor_sync(0xFFFFFFFFu, h0, 1);
        float p1 = __shfl_xor_sync(0xFFFFFFFFu, h1, 1);
        float va, vb;
        if (tig & 1) { va = p1; vb = h1; }   // row gID+8, feats jp, jp+1
        else         { va = h0; vb = p0; }   // row gID,   feats jp, jp+1

        if (t < 511) {
            uint32_t hv = pack_h2(va, vb);
            uint32_t dsto = (uint32_t)(b ^ 1) * HBUFB + hoff;
            uint32_t mbo  = 8u * (b ^ 1);
#pragma unroll
            for (int p = 0; p < 8; ++p)
                st_async_b32(peer_hs[p] + dsto, hv, peer_mb[p] + mbo);
        }

        // fp32 h to output (off the critical path)
        *(float2*)(d_out + (size_t)t * BF + (size_t)mb * 4096 + myrow * 256 + dcol) =
            make_float2(va, vb);
    }

    asm volatile("barrier.cluster.arrive.aligned;" ::: "memory");
    asm volatile("barrier.cluster.wait.aligned;" ::: "memory");
}

extern "C" void kernel_launch(void* const* d_in, const int* in_sizes, int n_in,
                              void* d_out, int out_size) {
    const float* x   = (const float*)d_in[0];
    const float* lf  = (const float*)d_in[1];
    const float* Wi  = (const float*)d_in[2];
    const float* bi  = (const float*)d_in[3];
    const float* Wih = (const float*)d_in[4];
    const float* Whh = (const float*)d_in[5];
    const float* bih = (const float*)d_in[6];
    const float* bhh = (const float*)d_in[7];
    float* out = (float*)d_out;

    cudaFuncSetAttribute(step0_kernel, cudaFuncAttributeMaxDynamicSharedMemorySize, 98304);

    prep_kernel<<<1152, 256>>>(Wih, Whh, bih, bhh, Wi);
    init_kernel<<<32, 256>>>(x, bi);
    step0_kernel<<<128, 256, 98304>>>(lf, out);
    lstm_kernel<<<128, 256>>>(out);
}